// round 1
// baseline (speedup 1.0000x reference)
#include <cuda_runtime.h>
#include <math.h>

// Neural CDE (Tsit5, 511 steps) — one thread per batch element, fp32,
// weights broadcast from shared (column-major), per-thread state in shared.

#define Hh     32
#define WIDw   64
#define CINc   3
#define Tt     512
#define NSTEPS 511
#define NTHR   128
#define W3R    96   // H*CIN rows of w3

// Tsit5 coefficients (float32, matching jax f32 promotion of python floats)
__constant__ float cA[6][5] = {
    {0.f, 0.f, 0.f, 0.f, 0.f},
    {0.161f, 0.f, 0.f, 0.f, 0.f},
    {-0.008480655492356989f, 0.335480655492357f, 0.f, 0.f, 0.f},
    {2.8971530571054935f, -6.359448489975075f, 4.3622954328695815f, 0.f, 0.f},
    {5.325864828439257f, -11.748883564062828f, 7.4955393428898365f, -0.09249506636175525f, 0.f},
    {5.86145544294642f, -12.92096931784711f, 8.159367898576159f, -0.071584973281401f, -0.028269050394068383f}
};
__constant__ float cB[6] = {
    0.09646076681806523f, 0.01f, 0.4798896504144996f,
    1.379008574103742f, -3.290069515436081f, 2.324710524099774f
};

// shared layout (in floats)
#define OFF_W1 0                      // 32 x 64 (col-major: [i][j])
#define OFF_B1 (OFF_W1 + Hh*WIDw)     // 64
#define OFF_W2 (OFF_B1 + WIDw)        // 64 x 64 (col-major)
#define OFF_B2 (OFF_W2 + WIDw*WIDw)   // 64
#define OFF_W3 (OFF_B2 + WIDw)        // 64 x 96 (col-major: [j][r])
#define OFF_B3 (OFF_W3 + WIDw*W3R)    // 96
#define OFF_V  (OFF_B3 + W3R)         // 64 * NTHR (activations / stage input)
#define OFF_Z  (OFF_V + WIDw*NTHR)    // 32 * NTHR (hidden state)
#define OFF_K  (OFF_Z + Hh*NTHR)      // 6 * 32 * NTHR (Tsit5 stage slopes)
#define SMEM_FLOATS (OFF_K + 6*Hh*NTHR)
#define SMEM_BYTES (SMEM_FLOATS * sizeof(float))   // 197,504 B

__global__ void __launch_bounds__(NTHR, 1)
ncde_kernel(const float* __restrict__ times,
            const float* __restrict__ grad,
            const float* __restrict__ w1, const float* __restrict__ b1,
            const float* __restrict__ w2, const float* __restrict__ b2,
            const float* __restrict__ w3, const float* __restrict__ b3,
            const float* __restrict__ w_enc, const float* __restrict__ b_enc,
            const float* __restrict__ w_ro, const float* __restrict__ b_ro,
            float* __restrict__ out, int Bn)
{
    extern __shared__ float sm[];
    float* sw1 = sm + OFF_W1;
    float* sb1 = sm + OFF_B1;
    float* sw2 = sm + OFF_W2;
    float* sb2 = sm + OFF_B2;
    float* sw3 = sm + OFF_W3;
    float* sb3 = sm + OFF_B3;
    float* vbuf = sm + OFF_V;
    float* zbuf = sm + OFF_Z;
    float* kbuf = sm + OFF_K;

    const int tid = threadIdx.x;

#define VB(i)    vbuf[(i)*NTHR + tid]
#define ZB(i)    zbuf[(i)*NTHR + tid]
#define KB(j,i)  kbuf[((j)*Hh + (i))*NTHR + tid]

    // --- load + transpose weights into shared (broadcast-friendly col-major) ---
    for (int idx = tid; idx < WIDw*Hh; idx += NTHR) {
        int j = idx / Hh, i = idx % Hh;           // w1[j][i]
        sw1[i*WIDw + j] = w1[idx];
    }
    for (int idx = tid; idx < WIDw; idx += NTHR) sb1[idx] = b1[idx];
    for (int idx = tid; idx < WIDw*WIDw; idx += NTHR) {
        int j = idx / WIDw, i = idx % WIDw;       // w2[j][i]
        sw2[i*WIDw + j] = w2[idx];
    }
    for (int idx = tid; idx < WIDw; idx += NTHR) sb2[idx] = b2[idx];
    for (int idx = tid; idx < W3R*WIDw; idx += NTHR) {
        int r = idx / WIDw, j = idx % WIDw;       // w3[r][j]
        sw3[j*W3R + r] = w3[idx];
    }
    for (int idx = tid; idx < W3R; idx += NTHR) sb3[idx] = b3[idx];
    __syncthreads();

    const int b = blockIdx.x * NTHR + tid;
    if (b < Bn) {
        // z0 = encoder([1.0]) = w_enc[:,0] + b_enc
        #pragma unroll
        for (int i = 0; i < Hh; ++i) ZB(i) = w_enc[i] + b_enc[i];

        const float dt = times[1] - times[0];
        const float* gp = grad + (long long)b * (Tt * CINc);

        for (int n = 0; n < NSTEPS; ++n) {
            const float dq0 = gp[n*3 + 0] * dt;
            const float dq1 = gp[n*3 + 1] * dt;
            const float dq2 = gp[n*3 + 2] * dt;

            for (int s = 0; s < 6; ++s) {
                // stage input zs = z + sum_j A[s][j] * k_j  -> vbuf[0..H)
                for (int i = 0; i < Hh; ++i) {
                    float zv = ZB(i);
                    for (int j = 0; j < s; ++j) zv += cA[s][j] * KB(j, i);
                    VB(i) = zv;
                }

                // ---- layer 1: t[64] = W1 @ zs + b1 ----
                float t[WIDw];
                #pragma unroll
                for (int j = 0; j < WIDw; ++j) t[j] = sb1[j];
                #pragma unroll 4
                for (int i = 0; i < Hh; ++i) {
                    const float x = VB(i);
                    const float4* wr = (const float4*)(sw1 + i*WIDw);
                    #pragma unroll
                    for (int j4 = 0; j4 < WIDw/4; ++j4) {
                        float4 w = wr[j4];
                        t[4*j4+0] += w.x * x;
                        t[4*j4+1] += w.y * x;
                        t[4*j4+2] += w.z * x;
                        t[4*j4+3] += w.w * x;
                    }
                }
                #pragma unroll
                for (int j = 0; j < WIDw; ++j) VB(j) = tanhf(t[j]);

                // ---- layer 2: t[64] = W2 @ h1 + b2 ----
                #pragma unroll
                for (int j = 0; j < WIDw; ++j) t[j] = sb2[j];
                #pragma unroll 4
                for (int i = 0; i < WIDw; ++i) {
                    const float x = VB(i);
                    const float4* wr = (const float4*)(sw2 + i*WIDw);
                    #pragma unroll
                    for (int j4 = 0; j4 < WIDw/4; ++j4) {
                        float4 w = wr[j4];
                        t[4*j4+0] += w.x * x;
                        t[4*j4+1] += w.y * x;
                        t[4*j4+2] += w.z * x;
                        t[4*j4+3] += w.w * x;
                    }
                }
                #pragma unroll
                for (int j = 0; j < WIDw; ++j) VB(j) = tanhf(t[j]);

                // ---- layer 3: u[96] = W3 @ h2 + b3, then contract with dq ----
                float u[W3R];
                #pragma unroll
                for (int r = 0; r < W3R; ++r) u[r] = sb3[r];
                #pragma unroll 4
                for (int i = 0; i < WIDw; ++i) {
                    const float x = VB(i);
                    const float4* wr = (const float4*)(sw3 + i*W3R);
                    #pragma unroll
                    for (int r4 = 0; r4 < W3R/4; ++r4) {
                        float4 w = wr[r4];
                        u[4*r4+0] += w.x * x;
                        u[4*r4+1] += w.y * x;
                        u[4*r4+2] += w.z * x;
                        u[4*r4+3] += w.w * x;
                    }
                }
                #pragma unroll
                for (int hh = 0; hh < Hh; ++hh) {
                    KB(s, hh) = u[3*hh+0]*dq0 + u[3*hh+1]*dq1 + u[3*hh+2]*dq2;
                }
            }

            // z += sum_j B[j] * k_j
            for (int i = 0; i < Hh; ++i) {
                float zv = ZB(i);
                #pragma unroll
                for (int j = 0; j < 6; ++j) zv += cB[j] * KB(j, i);
                ZB(i) = zv;
            }
        }

        // readout: sigmoid(z @ w_ro^T + b_ro)
        float logit = b_ro[0];
        for (int i = 0; i < Hh; ++i) logit += ZB(i) * w_ro[i];
        out[b] = 1.0f / (1.0f + expf(-logit));
    }
}

extern "C" void kernel_launch(void* const* d_in, const int* in_sizes, int n_in,
                              void* d_out, int out_size)
{
    const float* times = (const float*)d_in[0];
    const float* grad  = (const float*)d_in[1];
    const float* w1    = (const float*)d_in[2];
    const float* b1    = (const float*)d_in[3];
    const float* w2    = (const float*)d_in[4];
    const float* b2    = (const float*)d_in[5];
    const float* w3    = (const float*)d_in[6];
    const float* b3    = (const float*)d_in[7];
    const float* w_enc = (const float*)d_in[8];
    const float* b_enc = (const float*)d_in[9];
    const float* w_ro  = (const float*)d_in[10];
    const float* b_ro  = (const float*)d_in[11];
    float* out = (float*)d_out;

    const int Bn = in_sizes[1] / (Tt * CINc);
    const int nblocks = (Bn + NTHR - 1) / NTHR;

    cudaFuncSetAttribute(ncde_kernel,
                         cudaFuncAttributeMaxDynamicSharedMemorySize,
                         (int)SMEM_BYTES);
    ncde_kernel<<<nblocks, NTHR, SMEM_BYTES>>>(
        times, grad, w1, b1, w2, b2, w3, b3, w_enc, b_enc, w_ro, b_ro, out, Bn);
}

// round 2
// speedup vs baseline: 1.3692x; 1.3692x over previous
#include <cuda_runtime.h>
#include <math.h>

// Neural CDE (Tsit5, 511 steps) — 4 threads per batch element (output-sliced),
// packed fp32x2 FMA (FFMA2), Tsit5 state in registers, activations in shared.

#define Hh     32
#define WIDw   64
#define W3R    96
#define CINc   3
#define Tt     512
#define NSTEPS 511
#define NTHR   128
#define NELEM  32            // elements per CTA (4 threads each)
#define ESTRIDE 164          // per-element state floats: Y32 + V1 64 + V2 64 + pad4

// shared weight layout (floats)
#define OFF_W1 0                         // 32 x 64 col-major [i][j]
#define OFF_B1 (OFF_W1 + Hh*WIDw)        // 2048
#define OFF_W2 (OFF_B1 + WIDw)           // 2112
#define OFF_B2 (OFF_W2 + WIDw*WIDw)      // 6208
#define OFF_W3 (OFF_B2 + WIDw)           // 6272  (64 x 96 col-major [i][r])
#define OFF_B3 (OFF_W3 + WIDw*W3R)       // 12416
#define OFF_ST (OFF_B3 + W3R)            // 12512 (16B aligned in floats)
#define SMEM_FLOATS (OFF_ST + NELEM*ESTRIDE)
#define SMEM_BYTES  (SMEM_FLOATS * sizeof(float))   // 71,040 B -> 3 CTAs/SM

typedef unsigned long long u64;

__device__ __forceinline__ u64 pack2(float lo, float hi) {
    u64 r; asm("mov.b64 %0, {%1, %2};" : "=l"(r) : "f"(lo), "f"(hi)); return r;
}
__device__ __forceinline__ void unpack2(u64 v, float& lo, float& hi) {
    asm("mov.b64 {%0, %1}, %2;" : "=f"(lo), "=f"(hi) : "l"(v));
}
__device__ __forceinline__ u64 fma2(u64 a, u64 b, u64 c) {
    u64 d; asm("fma.rn.f32x2 %0, %1, %2, %3;" : "=l"(d) : "l"(a), "l"(b), "l"(c)); return d;
}
__device__ __forceinline__ u64 d2l(double x) { return __double_as_longlong(x); }

__global__ void __launch_bounds__(NTHR, 3)
ncde_kernel(const float* __restrict__ times,
            const float* __restrict__ grad,
            const float* __restrict__ w1, const float* __restrict__ b1,
            const float* __restrict__ w2, const float* __restrict__ b2,
            const float* __restrict__ w3, const float* __restrict__ b3,
            const float* __restrict__ w_enc, const float* __restrict__ b_enc,
            const float* __restrict__ w_ro, const float* __restrict__ b_ro,
            float* __restrict__ out, int Bn)
{
    extern __shared__ float sm[];
    const int tid = threadIdx.x;

    // Tsit5 coefficients as constexpr -> immediates after full unroll
    constexpr float TA[6][5] = {
        {0.f, 0.f, 0.f, 0.f, 0.f},
        {0.161f, 0.f, 0.f, 0.f, 0.f},
        {-0.008480655492356989f, 0.335480655492357f, 0.f, 0.f, 0.f},
        {2.8971530571054935f, -6.359448489975075f, 4.3622954328695815f, 0.f, 0.f},
        {5.325864828439257f, -11.748883564062828f, 7.4955393428898365f, -0.09249506636175525f, 0.f},
        {5.86145544294642f, -12.92096931784711f, 8.159367898576159f, -0.071584973281401f, -0.028269050394068383f}
    };
    constexpr float TB[6] = {
        0.09646076681806523f, 0.01f, 0.4798896504144996f,
        1.379008574103742f, -3.290069515436081f, 2.324710524099774f
    };

    // ---- load + transpose weights into shared (col-major by input index) ----
    for (int idx = tid; idx < WIDw*Hh; idx += NTHR) {
        int j = idx / Hh, i = idx % Hh;           // w1[j][i]
        sm[OFF_W1 + i*WIDw + j] = w1[idx];
    }
    for (int idx = tid; idx < WIDw; idx += NTHR) sm[OFF_B1 + idx] = b1[idx];
    for (int idx = tid; idx < WIDw*WIDw; idx += NTHR) {
        int j = idx / WIDw, i = idx % WIDw;       // w2[j][i]
        sm[OFF_W2 + i*WIDw + j] = w2[idx];
    }
    for (int idx = tid; idx < WIDw; idx += NTHR) sm[OFF_B2 + idx] = b2[idx];
    for (int idx = tid; idx < W3R*WIDw; idx += NTHR) {
        int r = idx / WIDw, j = idx % WIDw;       // w3[r][j]
        sm[OFF_W3 + j*W3R + r] = w3[idx];
    }
    for (int idx = tid; idx < W3R; idx += NTHR) sm[OFF_B3 + idx] = b3[idx];
    __syncthreads();

    const int lane = tid & 31;
    const int sl   = lane >> 3;        // slice 0..3 (output split)
    const int e    = lane & 7;         // element-within-warp
    const int warp = tid >> 5;
    const int el   = warp * 8 + e;     // element-within-CTA 0..31

    float* st = sm + OFF_ST + el * ESTRIDE;
    float* Yb = st;                    // stage input (32)
    float* V1 = st + 32;               // layer-1 activations (64)
    float* V2 = st + 96;               // layer-2 activations (64)

    const int  b      = blockIdx.x * NELEM + el;
    const bool is_act = (b < Bn);
    const int  bb     = is_act ? b : (Bn - 1);

    const float dt = times[1] - times[0];
    const float* gp = grad + (size_t)bb * (Tt * CINc);

    // Tsit5 state lives in registers (owner slice: h in [8*sl, 8*sl+8))
    float z[8], kst[6][8];
    #pragma unroll
    for (int j = 0; j < 8; ++j) z[j] = w_enc[8*sl + j] + b_enc[8*sl + j];

    float g0 = gp[0], g1 = gp[1], g2 = gp[2];

    for (int n = 0; n < NSTEPS; ++n) {
        const float dq0 = g0 * dt, dq1 = g1 * dt, dq2 = g2 * dt;
        if (n + 1 < NSTEPS) {
            const float* gn = gp + (n + 1) * 3;
            g0 = gn[0]; g1 = gn[1]; g2 = gn[2];
        }

        #pragma unroll
        for (int sg = 0; sg < 6; ++sg) {
            // ---- stage combine: y = z + sum_j A[sg][j] k_j  (own 8 dims) ----
            #pragma unroll
            for (int j = 0; j < 8; ++j) {
                float y = z[j];
                #pragma unroll
                for (int p = 0; p < 5; ++p)
                    if (p < sg) y += TA[sg][p] * kst[p][j];
                Yb[8*sl + j] = y;
            }
            __syncwarp();

            u64 a[12];

            // ---- layer 1: 16 outputs [16*sl, 16*sl+16) ----
            {
                const double* bias = (const double*)(sm + OFF_B1) + sl*8;
                #pragma unroll
                for (int q = 0; q < 8; ++q) a[q] = d2l(bias[q]);
                #pragma unroll 4
                for (int i = 0; i < Hh; ++i) {
                    const u64 xx = pack2(Yb[i], Yb[i]);
                    const double2* wr = (const double2*)(sm + OFF_W1 + i*WIDw + sl*16);
                    #pragma unroll
                    for (int q = 0; q < 4; ++q) {
                        double2 w = wr[q];
                        a[2*q]   = fma2(d2l(w.x), xx, a[2*q]);
                        a[2*q+1] = fma2(d2l(w.y), xx, a[2*q+1]);
                    }
                }
                #pragma unroll
                for (int q = 0; q < 8; ++q) {
                    float lo, hi; unpack2(a[q], lo, hi);
                    *(float2*)(V1 + sl*16 + 2*q) = make_float2(tanhf(lo), tanhf(hi));
                }
            }
            __syncwarp();

            // ---- layer 2: 16 outputs ----
            {
                const double* bias = (const double*)(sm + OFF_B2) + sl*8;
                #pragma unroll
                for (int q = 0; q < 8; ++q) a[q] = d2l(bias[q]);
                #pragma unroll 4
                for (int i = 0; i < WIDw; ++i) {
                    const u64 xx = pack2(V1[i], V1[i]);
                    const double2* wr = (const double2*)(sm + OFF_W2 + i*WIDw + sl*16);
                    #pragma unroll
                    for (int q = 0; q < 4; ++q) {
                        double2 w = wr[q];
                        a[2*q]   = fma2(d2l(w.x), xx, a[2*q]);
                        a[2*q+1] = fma2(d2l(w.y), xx, a[2*q+1]);
                    }
                }
                #pragma unroll
                for (int q = 0; q < 8; ++q) {
                    float lo, hi; unpack2(a[q], lo, hi);
                    *(float2*)(V2 + sl*16 + 2*q) = make_float2(tanhf(lo), tanhf(hi));
                }
            }
            __syncwarp();

            // ---- layer 3: 24 outputs [24*sl, 24*sl+24) + dq contraction ----
            {
                const double* bias = (const double*)(sm + OFF_B3) + sl*12;
                #pragma unroll
                for (int q = 0; q < 12; ++q) a[q] = d2l(bias[q]);
                #pragma unroll 4
                for (int i = 0; i < WIDw; ++i) {
                    const u64 xx = pack2(V2[i], V2[i]);
                    const double2* wr = (const double2*)(sm + OFF_W3 + i*W3R + sl*24);
                    #pragma unroll
                    for (int q = 0; q < 6; ++q) {
                        double2 w = wr[q];
                        a[2*q]   = fma2(d2l(w.x), xx, a[2*q]);
                        a[2*q+1] = fma2(d2l(w.y), xx, a[2*q+1]);
                    }
                }
                float u[24];
                #pragma unroll
                for (int q = 0; q < 12; ++q) unpack2(a[q], u[2*q], u[2*q+1]);
                #pragma unroll
                for (int h = 0; h < 8; ++h)
                    kst[sg][h] = u[3*h]*dq0 + u[3*h+1]*dq1 + u[3*h+2]*dq2;
            }
            // (no sync needed: K/Y are owner-private; hazards separated above)
        }

        // ---- z += sum_j B[j] k_j (own dims, registers) ----
        #pragma unroll
        for (int j = 0; j < 8; ++j) {
            float zz = z[j];
            #pragma unroll
            for (int p = 0; p < 6; ++p) zz += TB[p] * kst[p][j];
            z[j] = zz;
        }
    }

    // ---- readout: sigmoid(z . w_ro + b_ro), quad reduction via shfl ----
    float part = 0.f;
    #pragma unroll
    for (int j = 0; j < 8; ++j) part += z[j] * w_ro[8*sl + j];
    part += __shfl_xor_sync(0xffffffffu, part, 8);
    part += __shfl_xor_sync(0xffffffffu, part, 16);
    if (is_act && sl == 0)
        out[b] = 1.0f / (1.0f + expf(-(part + b_ro[0])));
}

extern "C" void kernel_launch(void* const* d_in, const int* in_sizes, int n_in,
                              void* d_out, int out_size)
{
    const float* times = (const float*)d_in[0];
    const float* grad  = (const float*)d_in[1];
    const float* w1    = (const float*)d_in[2];
    const float* b1    = (const float*)d_in[3];
    const float* w2    = (const float*)d_in[4];
    const float* b2    = (const float*)d_in[5];
    const float* w3    = (const float*)d_in[6];
    const float* b3    = (const float*)d_in[7];
    const float* w_enc = (const float*)d_in[8];
    const float* b_enc = (const float*)d_in[9];
    const float* w_ro  = (const float*)d_in[10];
    const float* b_ro  = (const float*)d_in[11];
    float* out = (float*)d_out;

    const int Bn = in_sizes[1] / (Tt * CINc);
    const int nblocks = (Bn + NELEM - 1) / NELEM;

    cudaFuncSetAttribute(ncde_kernel,
                         cudaFuncAttributeMaxDynamicSharedMemorySize,
                         (int)SMEM_BYTES);
    ncde_kernel<<<nblocks, NTHR, SMEM_BYTES>>>(
        times, grad, w1, b1, w2, b2, w3, b3, w_enc, b_enc, w_ro, b_ro, out, Bn);
}

// round 3
// speedup vs baseline: 2.0015x; 1.4617x over previous
#include <cuda_runtime.h>
#include <math.h>

// Neural CDE (Tsit5, 511 steps) — 4 threads x 2 packed elements per pair,
// f32x2 FMA everywhere, interleaved bank-conflict-free smem layouts.

#define Hh     32
#define WIDw   64
#define W3R    96
#define CINc   3
#define Tt     512
#define NSTEPS 511
#define NTHR   128
#define NPAIR  32            // element-pairs per CTA
#define NELEM  64            // elements per CTA

// weight region offsets (floats)
#define OFF_W1 0
#define OFF_B1 (OFF_W1 + Hh*WIDw)        // 2048
#define OFF_W2 (OFF_B1 + WIDw)           // 2112
#define OFF_B2 (OFF_W2 + WIDw*WIDw)      // 6208
#define OFF_W3 (OFF_B2 + WIDw)           // 6272
#define OFF_B3 (OFF_W3 + WIDw*W3R)       // 12416
#define OFF_WEND (OFF_B3 + W3R)          // 12512 floats (50048 B, 16B aligned)

#define PSTRIDE 161                      // u64 per pair: Y32 + V1 64 + V2 64 + pad1
#define SMEM_FLOATS (OFF_WEND + NPAIR*PSTRIDE*2)
#define SMEM_BYTES  (SMEM_FLOATS * 4)    // 50048 + 41216 = 91264 -> 2 CTAs/SM

typedef unsigned long long u64;

// zero-padded Tsit5 A (row s holds coeffs for k_0..k_4; zeros beyond)
__constant__ float cA6[6][5] = {
    {0.f, 0.f, 0.f, 0.f, 0.f},
    {0.161f, 0.f, 0.f, 0.f, 0.f},
    {-0.008480655492356989f, 0.335480655492357f, 0.f, 0.f, 0.f},
    {2.8971530571054935f, -6.359448489975075f, 4.3622954328695815f, 0.f, 0.f},
    {5.325864828439257f, -11.748883564062828f, 7.4955393428898365f, -0.09249506636175525f, 0.f},
    {5.86145544294642f, -12.92096931784711f, 8.159367898576159f, -0.071584973281401f, -0.028269050394068383f}
};

__device__ __forceinline__ u64 pack2(float lo, float hi) {
    u64 r; asm("mov.b64 %0, {%1, %2};" : "=l"(r) : "f"(lo), "f"(hi)); return r;
}
__device__ __forceinline__ void unpack2(u64 v, float& lo, float& hi) {
    asm("mov.b64 {%0, %1}, %2;" : "=f"(lo), "=f"(hi) : "l"(v));
}
__device__ __forceinline__ u64 fma2(u64 a, u64 b, u64 c) {
    u64 d; asm("fma.rn.f32x2 %0, %1, %2, %3;" : "=l"(d) : "l"(a), "l"(b), "l"(c)); return d;
}
__device__ __forceinline__ u64 d2l(double x) { return __double_as_longlong(x); }

// output-index permutations (bank-conflict-free interleave)
__device__ __forceinline__ int jmap(int p)  {  // 64-wide: slot p -> logical j
    int q = p >> 4, s = (p >> 2) & 3, c = p & 3;
    return s*16 + q*4 + c;
}
__device__ __forceinline__ int j3map(int p) {  // 96-wide
    int q = p >> 4, s = (p >> 2) & 3, c = p & 3;
    return s*24 + q*4 + c;
}

// GEMM slice: NQ output-chunks (4 outs each) for 2 packed elements.
template<int NI, int NQ, int ROWF>
__device__ __forceinline__ void gemm_slice(const u64* __restrict__ act,
                                           const float* __restrict__ wbase,  // + sl*4 already
                                           const float* __restrict__ biasbase, // + sl*4 already
                                           u64* a01, u64* a23, u64* b01, u64* b23)
{
    #pragma unroll
    for (int q = 0; q < NQ; ++q) {
        u64 bv01 = *(const u64*)(biasbase + q*16);
        u64 bv23 = *(const u64*)(biasbase + q*16 + 2);
        a01[q] = bv01; a23[q] = bv23; b01[q] = bv01; b23[q] = bv23;
    }
    #pragma unroll 4
    for (int i = 0; i < NI; ++i) {
        float2 x = ((const float2*)act)[i];
        u64 xa = pack2(x.x, x.x);
        u64 xb = pack2(x.y, x.y);
        const float* wr = wbase + i*ROWF;
        #pragma unroll
        for (int q = 0; q < NQ; ++q) {
            double2 wd = *(const double2*)(wr + q*16);
            u64 w01 = d2l(wd.x), w23 = d2l(wd.y);
            a01[q] = fma2(w01, xa, a01[q]);
            a23[q] = fma2(w23, xa, a23[q]);
            b01[q] = fma2(w01, xb, b01[q]);
            b23[q] = fma2(w23, xb, b23[q]);
        }
    }
}

__global__ void __launch_bounds__(NTHR, 2)
ncde_kernel(const float* __restrict__ times,
            const float* __restrict__ grad,
            const float* __restrict__ w1, const float* __restrict__ b1,
            const float* __restrict__ w2, const float* __restrict__ b2,
            const float* __restrict__ w3, const float* __restrict__ b3,
            const float* __restrict__ w_enc, const float* __restrict__ b_enc,
            const float* __restrict__ w_ro, const float* __restrict__ b_ro,
            float* __restrict__ out, int Bn)
{
    extern __shared__ float sm[];
    const int tid = threadIdx.x;

    constexpr float TB[6] = {
        0.09646076681806523f, 0.01f, 0.4798896504144996f,
        1.379008574103742f, -3.290069515436081f, 2.324710524099774f
    };

    // ---- weight transposes into interleaved layouts ----
    for (int idx = tid; idx < Hh*WIDw; idx += NTHR) {
        int i = idx >> 6, p = idx & 63;
        sm[OFF_W1 + i*WIDw + p] = w1[jmap(p)*Hh + i];
    }
    for (int p = tid; p < WIDw; p += NTHR) sm[OFF_B1 + p] = b1[jmap(p)];
    for (int idx = tid; idx < WIDw*WIDw; idx += NTHR) {
        int ip = idx >> 6, p = idx & 63;
        sm[OFF_W2 + ip*WIDw + p] = w2[jmap(p)*WIDw + jmap(ip)];
    }
    for (int p = tid; p < WIDw; p += NTHR) sm[OFF_B2 + p] = b2[jmap(p)];
    for (int idx = tid; idx < WIDw*W3R; idx += NTHR) {
        int ip = idx / W3R, p = idx % W3R;
        sm[OFF_W3 + ip*W3R + p] = w3[j3map(p)*WIDw + jmap(ip)];
    }
    for (int p = tid; p < W3R; p += NTHR) sm[OFF_B3 + p] = b3[j3map(p)];
    __syncthreads();

    const int lane = tid & 31;
    const int sl   = lane >> 3;          // output slice 0..3
    const int e    = lane & 7;
    const int warp = tid >> 5;
    const int pr   = warp*8 + e;         // pair index 0..31

    u64* stp = (u64*)(sm + OFF_WEND) + pr * PSTRIDE;
    u64* Yp  = stp;                      // 32 dims
    u64* V1p = stp + 32;                 // 64
    u64* V2p = stp + 96;                 // 64

    const int  b0 = blockIdx.x * NELEM + 2*pr;
    const int  b1i = b0 + 1;
    const int  bb0 = (b0  < Bn) ? b0  : (Bn - 1);
    const int  bb1 = (b1i < Bn) ? b1i : (Bn - 1);

    const float dt = times[1] - times[0];
    const float* gpA = grad + (size_t)bb0 * (Tt * CINc);
    const float* gpB = grad + (size_t)bb1 * (Tt * CINc);

    // packed Tsit5 state
    u64 z[8], kst[6][8];
    #pragma unroll
    for (int j = 0; j < 8; ++j) {
        float v = w_enc[8*sl + j] + b_enc[8*sl + j];
        z[j] = pack2(v, v);
    }
    #pragma unroll
    for (int p = 0; p < 6; ++p)
        #pragma unroll
        for (int j = 0; j < 8; ++j) kst[p][j] = pack2(0.f, 0.f);

    u64 cB2[6];
    #pragma unroll
    for (int p = 0; p < 6; ++p) cB2[p] = pack2(TB[p], TB[p]);

    const float* w1b = sm + OFF_W1 + sl*4;
    const float* w2b = sm + OFF_W2 + sl*4;
    const float* w3b = sm + OFF_W3 + sl*4;
    const float* b1b = sm + OFF_B1 + sl*4;
    const float* b2b = sm + OFF_B2 + sl*4;
    const float* b3b = sm + OFF_B3 + sl*4;

    float gA0 = gpA[0], gA1 = gpA[1], gA2 = gpA[2];
    float gB0 = gpB[0], gB1 = gpB[1], gB2 = gpB[2];

    #pragma unroll 1
    for (int n = 0; n < NSTEPS; ++n) {
        const float dqA[3] = {gA0*dt, gA1*dt, gA2*dt};
        const float dqB[3] = {gB0*dt, gB1*dt, gB2*dt};
        if (n + 1 < NSTEPS) {
            const float* ga = gpA + (n+1)*3; gA0 = ga[0]; gA1 = ga[1]; gA2 = ga[2];
            const float* gb = gpB + (n+1)*3; gB0 = gb[0]; gB1 = gb[1]; gB2 = gb[2];
        }

        #pragma unroll 1
        for (int sg = 0; sg < 6; ++sg) {
            // ---- stage combine: Y = z + sum_p A[sg][p] k_p (own 8 dims) ----
            u64 cc[5];
            #pragma unroll
            for (int p = 0; p < 5; ++p) { float c = cA6[sg][p]; cc[p] = pack2(c, c); }
            #pragma unroll
            for (int j = 0; j < 8; ++j) {
                u64 y = z[j];
                #pragma unroll
                for (int p = 0; p < 5; ++p) y = fma2(cc[p], kst[p][j], y);
                Yp[8*sl + j] = y;
            }
            __syncwarp();

            u64 a01[6], a23[6], b01[6], b23[6];

            // ---- layer 1 ----
            gemm_slice<Hh, 4, WIDw>(Yp, w1b, b1b, a01, a23, b01, b23);
            #pragma unroll
            for (int q = 0; q < 4; ++q) {
                float f0A,f1A,f2A,f3A, f0B,f1B,f2B,f3B;
                unpack2(a01[q], f0A, f1A); unpack2(b01[q], f0B, f1B);
                unpack2(a23[q], f2A, f3A); unpack2(b23[q], f2B, f3B);
                u64* dst = V1p + q*16 + sl*4;
                dst[0] = pack2(tanhf(f0A), tanhf(f0B));
                dst[1] = pack2(tanhf(f1A), tanhf(f1B));
                dst[2] = pack2(tanhf(f2A), tanhf(f2B));
                dst[3] = pack2(tanhf(f3A), tanhf(f3B));
            }
            __syncwarp();

            // ---- layer 2 ----
            gemm_slice<WIDw, 4, WIDw>(V1p, w2b, b2b, a01, a23, b01, b23);
            #pragma unroll
            for (int q = 0; q < 4; ++q) {
                float f0A,f1A,f2A,f3A, f0B,f1B,f2B,f3B;
                unpack2(a01[q], f0A, f1A); unpack2(b01[q], f0B, f1B);
                unpack2(a23[q], f2A, f3A); unpack2(b23[q], f2B, f3B);
                u64* dst = V2p + q*16 + sl*4;
                dst[0] = pack2(tanhf(f0A), tanhf(f0B));
                dst[1] = pack2(tanhf(f1A), tanhf(f1B));
                dst[2] = pack2(tanhf(f2A), tanhf(f2B));
                dst[3] = pack2(tanhf(f3A), tanhf(f3B));
            }
            __syncwarp();

            // ---- layer 3 + dq contraction ----
            gemm_slice<WIDw, 6, W3R>(V2p, w3b, b3b, a01, a23, b01, b23);
            float uA[24], uB[24];
            #pragma unroll
            for (int q = 0; q < 6; ++q) {
                unpack2(a01[q], uA[4*q+0], uA[4*q+1]);
                unpack2(a23[q], uA[4*q+2], uA[4*q+3]);
                unpack2(b01[q], uB[4*q+0], uB[4*q+1]);
                unpack2(b23[q], uB[4*q+2], uB[4*q+3]);
            }
            float kA[8], kB[8];
            #pragma unroll
            for (int h = 0; h < 8; ++h) { kA[h] = 0.f; kB[h] = 0.f; }
            #pragma unroll
            for (int p3 = 0; p3 < 24; ++p3) {
                const int h = p3 / 3, ch = p3 % 3;
                kA[h] = fmaf(uA[p3], dqA[ch], kA[h]);
                kB[h] = fmaf(uB[p3], dqB[ch], kB[h]);
            }
            #pragma unroll
            for (int p = 0; p < 6; ++p)
                if (p == sg) {
                    #pragma unroll
                    for (int h = 0; h < 8; ++h) kst[p][h] = pack2(kA[h], kB[h]);
                }
        }

        // ---- z += sum_p B[p] k_p ----
        #pragma unroll
        for (int j = 0; j < 8; ++j) {
            u64 zz = z[j];
            #pragma unroll
            for (int p = 0; p < 6; ++p) zz = fma2(cB2[p], kst[p][j], zz);
            z[j] = zz;
        }
    }

    // ---- readout ----
    float pA = 0.f, pB = 0.f;
    #pragma unroll
    for (int j = 0; j < 8; ++j) {
        float za, zb; unpack2(z[j], za, zb);
        const float wr = w_ro[8*sl + j];
        pA = fmaf(za, wr, pA);
        pB = fmaf(zb, wr, pB);
    }
    pA += __shfl_xor_sync(0xffffffffu, pA, 8);
    pA += __shfl_xor_sync(0xffffffffu, pA, 16);
    pB += __shfl_xor_sync(0xffffffffu, pB, 8);
    pB += __shfl_xor_sync(0xffffffffu, pB, 16);
    if (sl == 0) {
        const float br = b_ro[0];
        if (b0  < Bn) out[b0]  = 1.0f / (1.0f + expf(-(pA + br)));
        if (b1i < Bn) out[b1i] = 1.0f / (1.0f + expf(-(pB + br)));
    }
}

extern "C" void kernel_launch(void* const* d_in, const int* in_sizes, int n_in,
                              void* d_out, int out_size)
{
    const float* times = (const float*)d_in[0];
    const float* grad  = (const float*)d_in[1];
    const float* w1    = (const float*)d_in[2];
    const float* b1    = (const float*)d_in[3];
    const float* w2    = (const float*)d_in[4];
    const float* b2    = (const float*)d_in[5];
    const float* w3    = (const float*)d_in[6];
    const float* b3    = (const float*)d_in[7];
    const float* w_enc = (const float*)d_in[8];
    const float* b_enc = (const float*)d_in[9];
    const float* w_ro  = (const float*)d_in[10];
    const float* b_ro  = (const float*)d_in[11];
    float* out = (float*)d_out;

    const int Bn = in_sizes[1] / (Tt * CINc);
    const int nblocks = (Bn + NELEM - 1) / NELEM;

    cudaFuncSetAttribute(ncde_kernel,
                         cudaFuncAttributeMaxDynamicSharedMemorySize,
                         (int)SMEM_BYTES);
    ncde_kernel<<<nblocks, NTHR, SMEM_BYTES>>>(
        times, grad, w1, b1, w2, b2, w3, b3, w_enc, b_enc, w_ro, b_ro, out, Bn);
}